// round 1
// baseline (speedup 1.0000x reference)
#include <cuda_runtime.h>
#include <cuda_bf16.h>
#include <math.h>

// Problem constants
#define BQ 2048
#define KQ 49
#define DQ 2048

// Scratch (static device allocation is allowed)
__device__ float g_wgt[(size_t)BQ * KQ];   // W_gt[b][k] = dot(h_t[b], W_g[k])
__device__ float g_sent[BQ];               // sent logit per batch

// ---------------------------------------------------------------------------
// f32x2 packed FMA (Blackwell): acc.{lo,hi} += a.{lo,hi} * b.{lo,hi}
// ---------------------------------------------------------------------------
__device__ __forceinline__ void fma2(unsigned long long& acc,
                                     unsigned long long a,
                                     unsigned long long b) {
    asm("fma.rn.f32x2 %0, %1, %2, %0;" : "+l"(acc) : "l"(a), "l"(b));
}
__device__ __forceinline__ float2 unpack2(unsigned long long v) {
    float lo, hi;
    asm("mov.b64 {%0, %1}, %2;" : "=f"(lo), "=f"(hi) : "l"(v));
    return make_float2(lo, hi);
}

// ---------------------------------------------------------------------------
// Kernel A: W_gt[b][k] = h_t[b] . W_g[k],  sent[b] = sum_k tanh(s_t[b].W_s[k]
//            + W_gt[b][k]) * w_h_s[k]
// Grid: 128 CTAs x 256 threads, 16 batches per CTA. Tiled over D in chunks of 64.
// ---------------------------------------------------------------------------
#define A_BM 16
#define A_DC 64
#define A_STR 68   // row stride (floats), multiple of 4 for float4 stores

__global__ void __launch_bounds__(256) k_wgt_sent(
    const float* __restrict__ h_t, const float* __restrict__ s_t,
    const float* __restrict__ W_g, const float* __restrict__ W_s,
    const float* __restrict__ w_h_s)
{
    __shared__ float sh[A_BM * A_STR];
    __shared__ float ss[A_BM * A_STR];
    __shared__ float sg[64 * A_STR];
    __shared__ float sw[64 * A_STR];

    const int tid = threadIdx.x;
    const int tx = tid & 15;   // k-group: k = tx + 16*j
    const int ty = tid >> 4;   // batch row 0..15
    const int b0 = blockIdx.x * A_BM;

    float accG[4] = {0.f, 0.f, 0.f, 0.f};
    float accS[4] = {0.f, 0.f, 0.f, 0.f};

    for (int c = 0; c < DQ; c += A_DC) {
        // h/s tiles: 16 rows x 16 float4 = 256 float4 -> one per thread
        {
            int r = tid >> 4, u = tid & 15;
            *(float4*)(sh + r * A_STR + 4 * u) =
                *(const float4*)(h_t + (size_t)(b0 + r) * DQ + c + 4 * u);
            *(float4*)(ss + r * A_STR + 4 * u) =
                *(const float4*)(s_t + (size_t)(b0 + r) * DQ + c + 4 * u);
        }
        // W tiles: 49 rows x 16 float4
        for (int t = tid; t < KQ * 16; t += 256) {
            int k = t >> 4, u = t & 15;
            *(float4*)(sg + k * A_STR + 4 * u) =
                *(const float4*)(W_g + (size_t)k * DQ + c + 4 * u);
            *(float4*)(sw + k * A_STR + 4 * u) =
                *(const float4*)(W_s + (size_t)k * DQ + c + 4 * u);
        }
        __syncthreads();

        #pragma unroll 8
        for (int p = 0; p < A_DC / 2; ++p) {
            float2 ah = *(const float2*)(sh + ty * A_STR + 2 * p);
            float2 as = *(const float2*)(ss + ty * A_STR + 2 * p);
            #pragma unroll
            for (int j = 0; j < 4; ++j) {
                int k = tx + 16 * j;
                float2 bg = *(const float2*)(sg + k * A_STR + 2 * p);
                float2 bs = *(const float2*)(sw + k * A_STR + 2 * p);
                accG[j] = fmaf(ah.x, bg.x, fmaf(ah.y, bg.y, accG[j]));
                accS[j] = fmaf(as.x, bs.x, fmaf(as.y, bs.y, accS[j]));
            }
        }
        __syncthreads();
    }

    // Epilogue: write W_gt, reduce sent across the 16 k-lanes of this ty group
    float part = 0.f;
    #pragma unroll
    for (int j = 0; j < 4; ++j) {
        int k = tx + 16 * j;
        if (k < KQ) {
            g_wgt[(size_t)(b0 + ty) * KQ + k] = accG[j];
            part += tanhf(accS[j] + accG[j]) * w_h_s[k];
        }
    }
    #pragma unroll
    for (int off = 8; off; off >>= 1)
        part += __shfl_xor_sync(0xffffffffu, part, off);
    if (tx == 0) g_sent[b0 + ty] = part;
}

// ---------------------------------------------------------------------------
// Kernel B: per-batch fused kernel.
//   Phase 1: 49x49 GEMM over D (f32x2), + W_gt, tanh, weight, reduce -> z[l]
//   Softmax over [z(49), sent] -> alpha/beta
//   Phase 2: c_t = alpha . V[b]  (V[b] re-read from L2), output combine.
// Thread layout: 256 threads; tx=lane (k = tx, tx+32), ty=warp (l = 7*ty+i).
// ---------------------------------------------------------------------------
#define B_DC  128
#define B_STR 132  // tile row stride in floats (multiple of 4 -> 16B aligned rows)
#define VS_ROWS 56
#define WS_ROWS 64
#define SMEM_B_BYTES 120000  // oversized to force occupancy 1 (L2 residency of V[b])

__global__ void __launch_bounds__(256) k_main(
    const float* __restrict__ V, const float* __restrict__ h_t,
    const float* __restrict__ s_t, const float* __restrict__ W_v,
    const float* __restrict__ w_h, float* __restrict__ out)
{
    extern __shared__ float sm[];
    float* Vs    = sm;                                 // 56 x 132
    float* Ws    = sm + VS_ROWS * B_STR;               // 64 x 132 (swizzled 16B units)
    float* sLog  = sm + VS_ROWS * B_STR + WS_ROWS * B_STR;  // 64
    float* sProb = sLog + 64;                               // 64

    const int tid = threadIdx.x;
    const int tx = tid & 31;
    const int ty = tid >> 5;
    const int b = blockIdx.x;
    const float* Vb = V + (size_t)b * KQ * DQ;

    unsigned long long acc[7][2];
    #pragma unroll
    for (int i = 0; i < 7; ++i) { acc[i][0] = 0ull; acc[i][1] = 0ull; }

    const int s0 = (tx >> 3) & 7;          // swizzle key for k = tx
    const int s1 = ((tx + 32) >> 3) & 7;   // swizzle key for k = tx+32

    for (int c = 0; c < DQ; c += B_DC) {
        // Load V tile (rows l<49) and W_v tile (rows k<49). 49*32 float4 each.
        for (int t = tid; t < KQ * 32; t += 256) {
            int r = t >> 5, u = t & 31;
            *(float4*)(Vs + r * B_STR + 4 * u) =
                *(const float4*)(Vb + (size_t)r * DQ + c + 4 * u);
            *(float4*)(Ws + r * B_STR + 4 * (u ^ ((r >> 3) & 7))) =
                *(const float4*)(W_v + (size_t)r * DQ + c + 4 * u);
        }
        __syncthreads();

        #pragma unroll 8
        for (int p = 0; p < B_DC / 2; ++p) {
            int uu = p >> 1;
            int e = (p & 1) << 1;
            unsigned long long w0 =
                *(const unsigned long long*)(Ws + tx * B_STR + 4 * (uu ^ s0) + e);
            unsigned long long w1 =
                *(const unsigned long long*)(Ws + (tx + 32) * B_STR + 4 * (uu ^ s1) + e);
            #pragma unroll
            for (int i = 0; i < 7; ++i) {
                unsigned long long v =
                    *(const unsigned long long*)(Vs + (ty * 7 + i) * B_STR + 2 * p);
                fma2(acc[i][0], v, w0);
                fma2(acc[i][1], v, w1);
            }
        }
        __syncthreads();
    }

    // ---- Phase-1 epilogue: z[l] = sum_k tanh(acc + wgt[k]) * w_h[k] ----
    float wh0 = 0.f, wg0 = 0.f, wh1 = 0.f, wg1 = 0.f;
    if (tx < KQ) { wh0 = w_h[tx]; wg0 = g_wgt[(size_t)b * KQ + tx]; }
    const int k1 = tx + 32;
    if (k1 < KQ) { wh1 = w_h[k1]; wg1 = g_wgt[(size_t)b * KQ + k1]; }

    #pragma unroll
    for (int i = 0; i < 7; ++i) {
        int l = ty * 7 + i;
        float2 a0 = unpack2(acc[i][0]);
        float2 a1 = unpack2(acc[i][1]);
        float z = tanhf(a0.x + a0.y + wg0) * wh0;
        if (k1 < KQ) z += tanhf(a1.x + a1.y + wg1) * wh1;
        #pragma unroll
        for (int off = 16; off; off >>= 1)
            z += __shfl_xor_sync(0xffffffffu, z, off);
        if (tx == 0 && l < KQ) sLog[l] = z;
    }
    if (tid == 0) sLog[KQ] = g_sent[b];
    __syncthreads();

    // ---- Softmax over 50 logits (warp 0) ----
    if (tid < 32) {
        float v0 = (tx < 50) ? sLog[tx] : -3.402823466e38f;
        float v1 = (tx < 18) ? sLog[tx + 32] : -3.402823466e38f;
        float m = fmaxf(v0, v1);
        #pragma unroll
        for (int off = 16; off; off >>= 1)
            m = fmaxf(m, __shfl_xor_sync(0xffffffffu, m, off));
        float e0 = (tx < 50) ? expf(v0 - m) : 0.f;
        float e1 = (tx < 18) ? expf(v1 - m) : 0.f;
        float ssum = e0 + e1;
        #pragma unroll
        for (int off = 16; off; off >>= 1)
            ssum += __shfl_xor_sync(0xffffffffu, ssum, off);
        float inv = 1.f / ssum;
        if (tx < 50) sProb[tx] = e0 * inv;
        if (tx < 18) sProb[tx + 32] = e1 * inv;
    }
    __syncthreads();

    // ---- Phase 2: c_t + combine ----
    const float beta = sProb[KQ];
    float pr[KQ];
    #pragma unroll
    for (int l = 0; l < KQ; ++l) pr[l] = sProb[l];

    const size_t base = (size_t)b * DQ;
    for (int d = tid; d < DQ; d += 256) {
        float cacc = 0.f;
        #pragma unroll
        for (int l = 0; l < KQ; ++l)
            cacc = fmaf(pr[l], __ldg(Vb + (size_t)l * DQ + d), cacc);
        out[base + d] = fmaf(beta, s_t[base + d],
                        fmaf(1.f - beta, cacc, h_t[base + d]));
    }
}

// ---------------------------------------------------------------------------
extern "C" void kernel_launch(void* const* d_in, const int* in_sizes, int n_in,
                              void* d_out, int out_size) {
    (void)in_sizes; (void)n_in; (void)out_size;
    const float* V     = (const float*)d_in[0];
    const float* h_t   = (const float*)d_in[1];
    const float* s_t   = (const float*)d_in[2];
    const float* W_v   = (const float*)d_in[3];
    const float* W_g   = (const float*)d_in[4];
    const float* W_s   = (const float*)d_in[5];
    const float* w_h   = (const float*)d_in[6];
    const float* w_h_s = (const float*)d_in[7];
    float* out = (float*)d_out;

    k_wgt_sent<<<BQ / A_BM / 8 /* = 16? no: */ + 112, 256>>>(h_t, s_t, W_g, W_s, w_h_s);
    // NOTE: grid must cover exactly BQ/A_BM = 128 CTAs; the expression above is
    // wrong-proof only if it equals 128. Compute it explicitly instead:
    // (kept simple and exact below)

    cudaFuncSetAttribute(k_main, cudaFuncAttributeMaxDynamicSharedMemorySize,
                         SMEM_B_BYTES);
    k_main<<<BQ, 256, SMEM_B_BYTES>>>(V, h_t, s_t, W_v, w_h, out);
}

// round 4
// speedup vs baseline: 1.3212x; 1.3212x over previous
#include <cuda_runtime.h>
#include <cuda_bf16.h>
#include <mma.h>
#include <math.h>
#include <stdint.h>

using namespace nvcuda;

// Problem constants
#define BQ 2048
#define KQ 49
#define DQ 2048

// Scratch
__device__ float g_wgt[(size_t)BQ * KQ];   // W_gt[b][k]
__device__ float g_sent[BQ];               // sent logit per batch

// ---------------------------------------------------------------------------
// Kernel A: W_gt[b][k] = h_t[b] . W_g[k],  sent[b] = sum_k tanh(s_t[b].W_s[k]
//            + W_gt[b][k]) * w_h_s[k]
// ---------------------------------------------------------------------------
#define A_BM 16
#define A_DC 64
#define A_STR 68

__global__ void __launch_bounds__(256) k_wgt_sent(
    const float* __restrict__ h_t, const float* __restrict__ s_t,
    const float* __restrict__ W_g, const float* __restrict__ W_s,
    const float* __restrict__ w_h_s)
{
    __shared__ float sh[A_BM * A_STR];
    __shared__ float ss[A_BM * A_STR];
    __shared__ float sg[64 * A_STR];
    __shared__ float sw[64 * A_STR];

    const int tid = threadIdx.x;
    const int tx = tid & 15;
    const int ty = tid >> 4;
    const int b0 = blockIdx.x * A_BM;

    float accG[4] = {0.f, 0.f, 0.f, 0.f};
    float accS[4] = {0.f, 0.f, 0.f, 0.f};

    for (int c = 0; c < DQ; c += A_DC) {
        {
            int r = tid >> 4, u = tid & 15;
            *(float4*)(sh + r * A_STR + 4 * u) =
                *(const float4*)(h_t + (size_t)(b0 + r) * DQ + c + 4 * u);
            *(float4*)(ss + r * A_STR + 4 * u) =
                *(const float4*)(s_t + (size_t)(b0 + r) * DQ + c + 4 * u);
        }
        for (int t = tid; t < KQ * 16; t += 256) {
            int k = t >> 4, u = t & 15;
            *(float4*)(sg + k * A_STR + 4 * u) =
                *(const float4*)(W_g + (size_t)k * DQ + c + 4 * u);
            *(float4*)(sw + k * A_STR + 4 * u) =
                *(const float4*)(W_s + (size_t)k * DQ + c + 4 * u);
        }
        __syncthreads();

        #pragma unroll 8
        for (int p = 0; p < A_DC / 2; ++p) {
            float2 ah = *(const float2*)(sh + ty * A_STR + 2 * p);
            float2 as = *(const float2*)(ss + ty * A_STR + 2 * p);
            #pragma unroll
            for (int j = 0; j < 4; ++j) {
                int k = tx + 16 * j;
                float2 bg = *(const float2*)(sg + k * A_STR + 2 * p);
                float2 bs = *(const float2*)(sw + k * A_STR + 2 * p);
                accG[j] = fmaf(ah.x, bg.x, fmaf(ah.y, bg.y, accG[j]));
                accS[j] = fmaf(as.x, bs.x, fmaf(as.y, bs.y, accS[j]));
            }
        }
        __syncthreads();
    }

    float part = 0.f;
    #pragma unroll
    for (int j = 0; j < 4; ++j) {
        int k = tx + 16 * j;
        if (k < KQ) {
            g_wgt[(size_t)(b0 + ty) * KQ + k] = accG[j];
            part += tanhf(accS[j] + accG[j]) * w_h_s[k];
        }
    }
    #pragma unroll
    for (int off = 8; off; off >>= 1)
        part += __shfl_xor_sync(0xffffffffu, part, off);
    if (tx == 0) g_sent[b0 + ty] = part;
}

// ---------------------------------------------------------------------------
// Main kernel: per-batch WMMA tf32 GEMM (64x64x2048) + fused epilogue + phase 2
// ---------------------------------------------------------------------------
#define KC 32                    // fp32 elems per K chunk
#define NCHUNK (DQ / KC)         // 64
#define T_STR 36                 // tile stride (floats): 144B, 16B-multiple
#define C_STR 68                 // C scratch stride

// smem layout (floats)
#define F_A0   0                 // 64 x 36
#define F_A1   2304
#define F_B0   4608
#define F_B1   6912
#define F_END  9216              // tile region 36864 B; C scratch reuses F_A0
#define F_WGT  9216
#define F_WH   9280
#define F_LOG  9344
#define F_PROB 9408
#define SMEM_BYTES 200704        // oversized: forces occupancy 1 (V[b] L2-resident)

__device__ __forceinline__ uint32_t smem_u32(const void* p) {
    return (uint32_t)__cvta_generic_to_shared(p);
}
__device__ __forceinline__ void cp16(uint32_t dst, const void* src) {
    asm volatile("cp.async.cg.shared.global [%0], [%1], 16;" :: "r"(dst), "l"(src));
}

__global__ void __launch_bounds__(256) k_main(
    const float* __restrict__ V, const float* __restrict__ h_t,
    const float* __restrict__ s_t, const float* __restrict__ W_v,
    const float* __restrict__ w_h, float* __restrict__ out)
{
    extern __shared__ float sm[];
    const int tid = threadIdx.x;
    const int wid = tid >> 5;
    const int b = blockIdx.x;
    const float* Vb = V + (size_t)b * KQ * DQ;

    // small preloads
    if (tid < 64) {
        sm[F_WH  + tid] = (tid < KQ) ? w_h[tid] : 0.f;
        sm[F_WGT + tid] = (tid < KQ) ? g_wgt[(size_t)b * KQ + tid] : 0.f;
    }

    // warp tile: rows 16*mi, cols 32*nh + {0,16}
    const int mi = wid >> 1;
    const int nh = wid & 1;

    wmma::fragment<wmma::accumulator, 16, 16, 8, float> acc[2];
    wmma::fill_fragment(acc[0], 0.f);
    wmma::fill_fragment(acc[1], 0.f);

    // ---- chunk loader: 49 rows x 32 floats for A (V[b]) and B (W_v) ----
    auto load_chunk = [&](int c, int buf) {
        float* As = sm + (buf ? F_A1 : F_A0);
        float* Bs = sm + (buf ? F_B1 : F_B0);
        const float* Ag = Vb  + c * KC;
        const float* Bg = W_v + c * KC;
        for (int t = tid; t < 2 * KQ * 8; t += 256) {
            int isB = (t >= KQ * 8);
            int tt  = isB ? t - KQ * 8 : t;
            int row = tt >> 3, u = tt & 7;
            const float* src = (isB ? Bg : Ag) + (size_t)row * DQ + 4 * u;
            cp16(smem_u32((isB ? Bs : As) + row * T_STR + 4 * u), src);
        }
        asm volatile("cp.async.commit_group;" ::: "memory");
    };

    load_chunk(0, 0);

    for (int c = 0; c < NCHUNK; ++c) {
        if (c + 1 < NCHUNK) {
            load_chunk(c + 1, (c + 1) & 1);
            asm volatile("cp.async.wait_group 1;" ::: "memory");
        } else {
            asm volatile("cp.async.wait_group 0;" ::: "memory");
        }
        __syncthreads();

        const float* As = sm + ((c & 1) ? F_A1 : F_A0);
        const float* Bs = sm + ((c & 1) ? F_B1 : F_B0);
        #pragma unroll
        for (int s = 0; s < 4; ++s) {
            wmma::fragment<wmma::matrix_a, 16, 16, 8, wmma::precision::tf32,
                           wmma::row_major> af;
            wmma::load_matrix_sync(af, As + mi * 16 * T_STR + s * 8, T_STR);
            #pragma unroll
            for (int e = 0; e < af.num_elements; ++e)
                af.x[e] = wmma::__float_to_tf32(af.x[e]);
            #pragma unroll
            for (int t = 0; t < 2; ++t) {
                wmma::fragment<wmma::matrix_b, 16, 16, 8, wmma::precision::tf32,
                               wmma::col_major> bf;
                wmma::load_matrix_sync(bf, Bs + (nh * 32 + t * 16) * T_STR + s * 8,
                                       T_STR);
                #pragma unroll
                for (int e = 0; e < bf.num_elements; ++e)
                    bf.x[e] = wmma::__float_to_tf32(bf.x[e]);
                wmma::mma_sync(acc[t], af, bf, acc[t]);
            }
        }
        __syncthreads();
    }

    // ---- store C to smem scratch (reuses tile buffers) ----
    float* Cs = sm;  // 64 x 68
    wmma::store_matrix_sync(Cs + mi * 16 * C_STR + nh * 32,      acc[0], C_STR,
                            wmma::mem_row_major);
    wmma::store_matrix_sync(Cs + mi * 16 * C_STR + nh * 32 + 16, acc[1], C_STR,
                            wmma::mem_row_major);
    __syncthreads();

    // ---- logits: 7 FULL warps (224 threads); 4 threads per row l ----
    // All 32 lanes of each participating warp are active, so the width-4
    // shuffle reduction is well-defined (the R3 hang was partial-warp
    // __shfl_xor_sync in warp 6).
    if (tid < 224) {
        const int l  = tid >> 2;          // 0..55
        const int kg = tid & 3;
        float z = 0.f;
        if (l < KQ) {
            #pragma unroll
            for (int j = 0; j < 13; ++j) {
                int k = kg + 4 * j;
                if (k < KQ)
                    z += tanhf(Cs[l * C_STR + k] + sm[F_WGT + k]) * sm[F_WH + k];
            }
        }
        z += __shfl_xor_sync(0xffffffffu, z, 1);
        z += __shfl_xor_sync(0xffffffffu, z, 2);
        if (kg == 0 && l < KQ) sm[F_LOG + l] = z;
    }
    if (tid == 0) sm[F_LOG + KQ] = g_sent[b];
    __syncthreads();

    // ---- softmax over 50 logits (warp 0, fully active) ----
    if (tid < 32) {
        int tx = tid;
        float v0 = (tx < 50) ? sm[F_LOG + tx] : -3.402823466e38f;
        float v1 = (tx < 18) ? sm[F_LOG + tx + 32] : -3.402823466e38f;
        float m = fmaxf(v0, v1);
        #pragma unroll
        for (int off = 16; off; off >>= 1)
            m = fmaxf(m, __shfl_xor_sync(0xffffffffu, m, off));
        float e0 = (tx < 50) ? expf(v0 - m) : 0.f;
        float e1 = (tx < 18) ? expf(v1 - m) : 0.f;
        float ssum = e0 + e1;
        #pragma unroll
        for (int off = 16; off; off >>= 1)
            ssum += __shfl_xor_sync(0xffffffffu, ssum, off);
        float inv = 1.f / ssum;
        if (tx < 50) sm[F_PROB + tx] = e0 * inv;
        if (tx < 18) sm[F_PROB + tx + 32] = e1 * inv;
    }
    __syncthreads();

    // ---- phase 2: c_t = alpha . V[b] (L2-resident), combine ----
    const float beta = sm[F_PROB + KQ];
    float pr[KQ];
    #pragma unroll
    for (int l = 0; l < KQ; ++l) pr[l] = sm[F_PROB + l];

    const size_t base = (size_t)b * DQ;
    for (int d = tid; d < DQ; d += 256) {
        float cacc = 0.f;
        #pragma unroll
        for (int l = 0; l < KQ; ++l)
            cacc = fmaf(pr[l], __ldg(Vb + (size_t)l * DQ + d), cacc);
        out[base + d] = fmaf(beta, s_t[base + d],
                        fmaf(1.f - beta, cacc, h_t[base + d]));
    }
}

// ---------------------------------------------------------------------------
extern "C" void kernel_launch(void* const* d_in, const int* in_sizes, int n_in,
                              void* d_out, int out_size) {
    (void)in_sizes; (void)n_in; (void)out_size;
    const float* V     = (const float*)d_in[0];
    const float* h_t   = (const float*)d_in[1];
    const float* s_t   = (const float*)d_in[2];
    const float* W_v   = (const float*)d_in[3];
    const float* W_g   = (const float*)d_in[4];
    const float* W_s   = (const float*)d_in[5];
    const float* w_h   = (const float*)d_in[6];
    const float* w_h_s = (const float*)d_in[7];
    float* out = (float*)d_out;

    k_wgt_sent<<<BQ / A_BM, 256>>>(h_t, s_t, W_g, W_s, w_h_s);

    cudaFuncSetAttribute(k_main, cudaFuncAttributeMaxDynamicSharedMemorySize,
                         SMEM_BYTES);
    k_main<<<BQ, 256, SMEM_BYTES>>>(V, h_t, s_t, W_v, w_h, out);
}

// round 8
// speedup vs baseline: 1.6847x; 1.2751x over previous
#include <cuda_runtime.h>
#include <cuda_bf16.h>
#include <mma.h>
#include <math.h>
#include <stdint.h>

using namespace nvcuda;

// Problem constants
#define BQ 2048
#define KQ 49
#define DQ 2048

// Scratch
__device__ float g_wgt[(size_t)BQ * KQ];   // W_gt[b][k]
__device__ float g_sent[BQ];               // sent logit per batch

// ---------------------------------------------------------------------------
// Kernel A: warp-per-row: 8 batch rows x 32 k-lanes per CTA (256 CTAs total)
// ---------------------------------------------------------------------------
#define A_BM 8
#define A_DC 64
#define A_STR 68

__global__ void __launch_bounds__(256) k_wgt_sent(
    const float* __restrict__ h_t, const float* __restrict__ s_t,
    const float* __restrict__ W_g, const float* __restrict__ W_s,
    const float* __restrict__ w_h_s)
{
    __shared__ float sh[A_BM * A_STR];
    __shared__ float ss[A_BM * A_STR];
    __shared__ float sg[64 * A_STR];
    __shared__ float sw[64 * A_STR];

    const int tid = threadIdx.x;
    const int tx = tid & 31;   // k-lane: k = tx, tx+32
    const int ty = tid >> 5;   // batch row 0..7 (one warp per row)
    const int b0 = blockIdx.x * A_BM;

    float accG[2] = {0.f, 0.f};
    float accS[2] = {0.f, 0.f};

    for (int c = 0; c < DQ; c += A_DC) {
        if (tid < A_BM * 16) {
            int r = tid >> 4, u = tid & 15;
            *(float4*)(sh + r * A_STR + 4 * u) =
                *(const float4*)(h_t + (size_t)(b0 + r) * DQ + c + 4 * u);
            *(float4*)(ss + r * A_STR + 4 * u) =
                *(const float4*)(s_t + (size_t)(b0 + r) * DQ + c + 4 * u);
        }
        for (int t = tid; t < KQ * 16; t += 256) {
            int k = t >> 4, u = t & 15;
            *(float4*)(sg + k * A_STR + 4 * u) =
                *(const float4*)(W_g + (size_t)k * DQ + c + 4 * u);
            *(float4*)(sw + k * A_STR + 4 * u) =
                *(const float4*)(W_s + (size_t)k * DQ + c + 4 * u);
        }
        __syncthreads();

        #pragma unroll 8
        for (int p = 0; p < A_DC / 2; ++p) {
            float2 ah = *(const float2*)(sh + ty * A_STR + 2 * p);
            float2 as = *(const float2*)(ss + ty * A_STR + 2 * p);
            #pragma unroll
            for (int j = 0; j < 2; ++j) {
                int k = tx + 32 * j;
                float2 bg = *(const float2*)(sg + k * A_STR + 2 * p);
                float2 bs = *(const float2*)(sw + k * A_STR + 2 * p);
                accG[j] = fmaf(ah.x, bg.x, fmaf(ah.y, bg.y, accG[j]));
                accS[j] = fmaf(as.x, bs.x, fmaf(as.y, bs.y, accS[j]));
            }
        }
        __syncthreads();
    }

    float part = 0.f;
    #pragma unroll
    for (int j = 0; j < 2; ++j) {
        int k = tx + 32 * j;
        if (k < KQ) {
            g_wgt[(size_t)(b0 + ty) * KQ + k] = accG[j];
            part += tanhf(accS[j] + accG[j]) * w_h_s[k];
        }
    }
    #pragma unroll
    for (int off = 16; off; off >>= 1)
        part += __shfl_xor_sync(0xffffffffu, part, off);
    if (tx == 0) g_sent[b0 + ty] = part;
}

// ---------------------------------------------------------------------------
// Main kernel: per-batch WMMA tf32 GEMM, 4-stage cp.async ring, occ 2
// ---------------------------------------------------------------------------
#define KC 32                    // fp32 elems per K chunk
#define NCHUNK (DQ / KC)         // 64
#define NSTAGE 4
#define T_STR 36                 // tile row stride (floats), 16B-multiple
#define C_STR 68

// smem layout (floats): stage s at s*4608 (A 64x36, then B 64x36)
#define STG_F    4608
#define STG_BYTES (STG_F * 4)    // 18432
#define F_WGT  (NSTAGE * STG_F)          // 18432
#define F_WH   (F_WGT + 64)
#define F_LOG  (F_WGT + 128)
#define F_PROB (F_WGT + 192)
#define SMEM_BYTES 101376        // 99KB -> exactly occupancy 2 (228KB carveout)

__device__ __forceinline__ uint32_t smem_u32(const void* p) {
    return (uint32_t)__cvta_generic_to_shared(p);
}
__device__ __forceinline__ void cp16(uint32_t dst, const void* src) {
    asm volatile("cp.async.cg.shared.global [%0], [%1], 16;" :: "r"(dst), "l"(src));
}

__global__ void __launch_bounds__(256) k_main(
    const float* __restrict__ V, const float* __restrict__ h_t,
    const float* __restrict__ s_t, const float* __restrict__ W_v,
    const float* __restrict__ w_h, float* __restrict__ out)
{
    extern __shared__ float sm[];
    const int tid = threadIdx.x;
    const int wid = tid >> 5;
    const int b = blockIdx.x;
    const float* Vb = V + (size_t)b * KQ * DQ;

    if (tid < 64) {
        sm[F_WH  + tid] = (tid < KQ) ? w_h[tid] : 0.f;
        sm[F_WGT + tid] = (tid < KQ) ? g_wgt[(size_t)b * KQ + tid] : 0.f;
    }

    // ---- precompute per-thread cp.async address table (once) ----
    // 2*49*8 = 784 16B-transfers; thread handles t = tid, tid+256, ...
    const float* srcs[4];
    uint32_t dsts[4];               // byte offsets for stage 0
    int nCp = 0;
    for (int t = tid; t < 2 * KQ * 8; t += 256) {
        int isB = (t >= KQ * 8);
        int tt  = isB ? t - KQ * 8 : t;
        int row = tt >> 3, u = tt & 7;
        srcs[nCp] = (isB ? W_v : Vb) + (size_t)row * DQ + 4 * u;
        dsts[nCp] = smem_u32(sm + (isB ? 2304 : 0) + row * T_STR + 4 * u);
        nCp++;
    }

    auto issue_chunk = [&](int cc) {
        const uint32_t stg = (uint32_t)(cc & 3) * STG_BYTES;
        const int off = cc * KC;
        #pragma unroll
        for (int j = 0; j < 4; ++j)
            if (j < nCp) cp16(dsts[j] + stg, srcs[j] + off);
    };

    // warp tile: rows 16*mi, cols 32*nh + {0,16}
    const int mi = wid >> 1;
    const int nh = wid & 1;

    wmma::fragment<wmma::accumulator, 16, 16, 8, float> acc[2];
    wmma::fill_fragment(acc[0], 0.f);
    wmma::fill_fragment(acc[1], 0.f);

    // prologue: stages for chunks 0..2
    issue_chunk(0); asm volatile("cp.async.commit_group;" ::: "memory");
    issue_chunk(1); asm volatile("cp.async.commit_group;" ::: "memory");
    issue_chunk(2); asm volatile("cp.async.commit_group;" ::: "memory");

    for (int c = 0; c < NCHUNK; ++c) {
        asm volatile("cp.async.wait_group 2;" ::: "memory");
        __syncthreads();                  // chunk c visible; frees stage (c-1)&3
        if (c + 3 < NCHUNK) issue_chunk(c + 3);
        asm volatile("cp.async.commit_group;" ::: "memory");  // may be empty

        const float* St = sm + (c & 3) * STG_F;   // A at +0, B at +2304
        #pragma unroll
        for (int s = 0; s < 4; ++s) {
            wmma::fragment<wmma::matrix_a, 16, 16, 8, wmma::precision::tf32,
                           wmma::row_major> af;
            wmma::load_matrix_sync(af, St + mi * 16 * T_STR + s * 8, T_STR);
            #pragma unroll
            for (int e = 0; e < af.num_elements; ++e)
                af.x[e] = wmma::__float_to_tf32(af.x[e]);
            #pragma unroll
            for (int t = 0; t < 2; ++t) {
                wmma::fragment<wmma::matrix_b, 16, 16, 8, wmma::precision::tf32,
                               wmma::col_major> bf;
                wmma::load_matrix_sync(bf, St + 2304 + (nh * 32 + t * 16) * T_STR
                                           + s * 8, T_STR);
                #pragma unroll
                for (int e = 0; e < bf.num_elements; ++e)
                    bf.x[e] = wmma::__float_to_tf32(bf.x[e]);
                wmma::mma_sync(acc[t], af, bf, acc[t]);
            }
        }
    }
    __syncthreads();   // all compute done before C scratch overwrites stages 0/1

    // ---- store C (64x68) into stage-0/1 region ----
    float* Cs = sm;
    wmma::store_matrix_sync(Cs + mi * 16 * C_STR + nh * 32,      acc[0], C_STR,
                            wmma::mem_row_major);
    wmma::store_matrix_sync(Cs + mi * 16 * C_STR + nh * 32 + 16, acc[1], C_STR,
                            wmma::mem_row_major);
    __syncthreads();

    // ---- logits: 7 FULL warps; 4 threads per row l (width-4 shuffle) ----
    if (tid < 224) {
        const int l  = tid >> 2;          // 0..55
        const int kg = tid & 3;
        float z = 0.f;
        if (l < KQ) {
            #pragma unroll
            for (int j = 0; j < 13; ++j) {
                int k = kg + 4 * j;
                if (k < KQ)
                    z += tanhf(Cs[l * C_STR + k] + sm[F_WGT + k]) * sm[F_WH + k];
            }
        }
        z += __shfl_xor_sync(0xffffffffu, z, 1);
        z += __shfl_xor_sync(0xffffffffu, z, 2);
        if (kg == 0 && l < KQ) sm[F_LOG + l] = z;
    }
    if (tid == 0) sm[F_LOG + KQ] = g_sent[b];
    __syncthreads();

    // ---- softmax over 50 logits (warp 0) ----
    if (tid < 32) {
        int tx = tid;
        float v0 = (tx < 50) ? sm[F_LOG + tx] : -3.402823466e38f;
        float v1 = (tx < 18) ? sm[F_LOG + tx + 32] : -3.402823466e38f;
        float m = fmaxf(v0, v1);
        #pragma unroll
        for (int off = 16; off; off >>= 1)
            m = fmaxf(m, __shfl_xor_sync(0xffffffffu, m, off));
        float e0 = (tx < 50) ? expf(v0 - m) : 0.f;
        float e1 = (tx < 18) ? expf(v1 - m) : 0.f;
        float ssum = e0 + e1;
        #pragma unroll
        for (int off = 16; off; off >>= 1)
            ssum += __shfl_xor_sync(0xffffffffu, ssum, off);
        float inv = 1.f / ssum;
        if (tx < 50) sm[F_PROB + tx] = e0 * inv;
        if (tx < 18) sm[F_PROB + tx + 32] = e1 * inv;
    }
    __syncthreads();

    // ---- phase 2: c_t = alpha . V[b], combine ----
    const float beta = sm[F_PROB + KQ];
    float pr[KQ];
    #pragma unroll
    for (int l = 0; l < KQ; ++l) pr[l] = sm[F_PROB + l];

    const size_t base = (size_t)b * DQ;
    for (int d = tid; d < DQ; d += 256) {
        float cacc = 0.f;
        #pragma unroll
        for (int l = 0; l < KQ; ++l)
            cacc = fmaf(pr[l], __ldg(Vb + (size_t)l * DQ + d), cacc);
        out[base + d] = fmaf(beta, s_t[base + d],
                        fmaf(1.f - beta, cacc, h_t[base + d]));
    }
}

// ---------------------------------------------------------------------------
extern "C" void kernel_launch(void* const* d_in, const int* in_sizes, int n_in,
                              void* d_out, int out_size) {
    (void)in_sizes; (void)n_in; (void)out_size;
    const float* V     = (const float*)d_in[0];
    const float* h_t   = (const float*)d_in[1];
    const float* s_t   = (const float*)d_in[2];
    const float* W_v   = (const float*)d_in[3];
    const float* W_g   = (const float*)d_in[4];
    const float* W_s   = (const float*)d_in[5];
    const float* w_h   = (const float*)d_in[6];
    const float* w_h_s = (const float*)d_in[7];
    float* out = (float*)d_out;

    k_wgt_sent<<<BQ / A_BM, 256>>>(h_t, s_t, W_g, W_s, w_h_s);

    cudaFuncSetAttribute(k_main, cudaFuncAttributeMaxDynamicSharedMemorySize,
                         SMEM_BYTES);
    k_main<<<BQ, 256, SMEM_BYTES>>>(V, h_t, s_t, W_v, w_h, out);
}

// round 9
// speedup vs baseline: 2.5188x; 1.4952x over previous
#include <cuda_runtime.h>
#include <cuda_bf16.h>
#include <mma.h>
#include <math.h>
#include <stdint.h>

using namespace nvcuda;

// Problem constants
#define BQ 2048
#define KQ 49
#define DQ 2048

// Scratch
__device__ float g_wgt[(size_t)BQ * KQ];   // W_gt[b][k]
__device__ float g_sent[BQ];               // sent logit per batch

// ---------------------------------------------------------------------------
// Kernel A: warp-per-row: 8 batch rows x 32 k-lanes per CTA (256 CTAs total)
// ---------------------------------------------------------------------------
#define A_BM 8
#define A_DC 64
#define A_STR 68

__global__ void __launch_bounds__(256) k_wgt_sent(
    const float* __restrict__ h_t, const float* __restrict__ s_t,
    const float* __restrict__ W_g, const float* __restrict__ W_s,
    const float* __restrict__ w_h_s)
{
    __shared__ float sh[A_BM * A_STR];
    __shared__ float ss[A_BM * A_STR];
    __shared__ float sg[64 * A_STR];
    __shared__ float sw[64 * A_STR];

    const int tid = threadIdx.x;
    const int tx = tid & 31;
    const int ty = tid >> 5;
    const int b0 = blockIdx.x * A_BM;

    float accG[2] = {0.f, 0.f};
    float accS[2] = {0.f, 0.f};

    for (int c = 0; c < DQ; c += A_DC) {
        if (tid < A_BM * 16) {
            int r = tid >> 4, u = tid & 15;
            *(float4*)(sh + r * A_STR + 4 * u) =
                *(const float4*)(h_t + (size_t)(b0 + r) * DQ + c + 4 * u);
            *(float4*)(ss + r * A_STR + 4 * u) =
                *(const float4*)(s_t + (size_t)(b0 + r) * DQ + c + 4 * u);
        }
        for (int t = tid; t < KQ * 16; t += 256) {
            int k = t >> 4, u = t & 15;
            *(float4*)(sg + k * A_STR + 4 * u) =
                *(const float4*)(W_g + (size_t)k * DQ + c + 4 * u);
            *(float4*)(sw + k * A_STR + 4 * u) =
                *(const float4*)(W_s + (size_t)k * DQ + c + 4 * u);
        }
        __syncthreads();

        #pragma unroll 8
        for (int p = 0; p < A_DC / 2; ++p) {
            float2 ah = *(const float2*)(sh + ty * A_STR + 2 * p);
            float2 as = *(const float2*)(ss + ty * A_STR + 2 * p);
            #pragma unroll
            for (int j = 0; j < 2; ++j) {
                int k = tx + 32 * j;
                float2 bg = *(const float2*)(sg + k * A_STR + 2 * p);
                float2 bs = *(const float2*)(sw + k * A_STR + 2 * p);
                accG[j] = fmaf(ah.x, bg.x, fmaf(ah.y, bg.y, accG[j]));
                accS[j] = fmaf(as.x, bs.x, fmaf(as.y, bs.y, accS[j]));
            }
        }
        __syncthreads();
    }

    float part = 0.f;
    #pragma unroll
    for (int j = 0; j < 2; ++j) {
        int k = tx + 32 * j;
        if (k < KQ) {
            g_wgt[(size_t)(b0 + ty) * KQ + k] = accG[j];
            part += tanhf(accS[j] + accG[j]) * w_h_s[k];
        }
    }
    #pragma unroll
    for (int off = 16; off; off >>= 1)
        part += __shfl_xor_sync(0xffffffffu, part, off);
    if (tx == 0) g_sent[b0 + ty] = part;
}

// ---------------------------------------------------------------------------
// Main kernel: 2 batches per CTA. WMMA tf32 GEMM M=128 N=64 K=2048,
// 4-stage cp.async ring, occ 2, no explicit tf32 rounding (HW truncation).
// ---------------------------------------------------------------------------
#define BPC 2                    // batches per CTA
#define KC 32                    // fp32 elems per K chunk
#define NCHUNK (DQ / KC)         // 64
#define T_STR 36                 // tile row stride (floats)
#define C_STR 68

// stage: A 128x36 (4608 f) then B 64x36 (2304 f)
#define STG_F 6912
#define STG_BYTES (STG_F * 4)    // 27648
#define F_B    4608              // B offset inside stage (floats)
#define F_WGT  (4 * STG_F)       // 27648: wgt[2][64]
#define F_WH   (F_WGT + 128)     // wh[64]
#define F_LOG  (F_WGT + 192)     // log[2][64]
#define F_PROB (F_WGT + 320)     // prob[2][64]
#define SMEM_BYTES 112640        // 110 KB -> occupancy 2

__device__ __forceinline__ uint32_t smem_u32(const void* p) {
    return (uint32_t)__cvta_generic_to_shared(p);
}
__device__ __forceinline__ void cp16(uint32_t dst, const void* src) {
    asm volatile("cp.async.cg.shared.global [%0], [%1], 16;" :: "r"(dst), "l"(src));
}

__global__ void __launch_bounds__(256) k_main(
    const float* __restrict__ V, const float* __restrict__ h_t,
    const float* __restrict__ s_t, const float* __restrict__ W_v,
    const float* __restrict__ w_h, float* __restrict__ out)
{
    extern __shared__ float sm[];
    const int tid = threadIdx.x;
    const int wid = tid >> 5;
    const int b = blockIdx.x;          // batch pair: batches 2b, 2b+1

    if (tid < 64)  sm[F_WH + tid] = (tid < KQ) ? w_h[tid] : 0.f;
    if (tid < 128) {
        int bt = tid >> 6, k = tid & 63;
        sm[F_WGT + tid] = (k < KQ) ? g_wgt[(size_t)(2 * b + bt) * KQ + k] : 0.f;
    }

    // ---- per-thread cp.async address table (once) ----
    // A: rows 0..127 (row = bt*64 + vr, vr<49 valid), B: rows 0..63 (<49).
    const float* srcs[6];
    uint32_t dsts[6];
    int nCp = 0;
    for (int t = tid; t < 1536; t += 256) {
        if (t < 1024) {                       // A transfers
            int row = t >> 3, u = t & 7;
            int bt = row >> 6, vr = row & 63;
            if (vr >= KQ) continue;
            srcs[nCp] = V + ((size_t)(2 * b + bt) * KQ + vr) * DQ + 4 * u;
            dsts[nCp] = smem_u32(sm + row * T_STR + 4 * u);
            nCp++;
        } else {                              // B transfers
            int tt = t - 1024;
            int row = tt >> 3, u = tt & 7;
            if (row >= KQ) continue;
            srcs[nCp] = W_v + (size_t)row * DQ + 4 * u;
            dsts[nCp] = smem_u32(sm + F_B + row * T_STR + 4 * u);
            nCp++;
        }
    }

    auto issue_chunk = [&](int cc) {
        const uint32_t stg = (uint32_t)(cc & 3) * STG_BYTES;
        const int off = cc * KC;
        #pragma unroll
        for (int j = 0; j < 6; ++j)
            if (j < nCp) cp16(dsts[j] + stg, srcs[j] + off);
    };

    // warp tile: rows 32*mi (mi=wid>>1), cols 32*nh (nh=wid&1); 2x2 fragments
    const int mi = wid >> 1;
    const int nh = wid & 1;

    wmma::fragment<wmma::accumulator, 16, 16, 8, float> acc[2][2];
    wmma::fill_fragment(acc[0][0], 0.f);
    wmma::fill_fragment(acc[0][1], 0.f);
    wmma::fill_fragment(acc[1][0], 0.f);
    wmma::fill_fragment(acc[1][1], 0.f);

    issue_chunk(0); asm volatile("cp.async.commit_group;" ::: "memory");
    issue_chunk(1); asm volatile("cp.async.commit_group;" ::: "memory");
    issue_chunk(2); asm volatile("cp.async.commit_group;" ::: "memory");

    for (int c = 0; c < NCHUNK; ++c) {
        asm volatile("cp.async.wait_group 2;" ::: "memory");
        __syncthreads();
        if (c + 3 < NCHUNK) issue_chunk(c + 3);
        asm volatile("cp.async.commit_group;" ::: "memory");

        const float* St = sm + (c & 3) * STG_F;
        #pragma unroll
        for (int s = 0; s < 4; ++s) {
            wmma::fragment<wmma::matrix_a, 16, 16, 8, wmma::precision::tf32,
                           wmma::row_major> af[2];
            wmma::load_matrix_sync(af[0], St + (mi * 32 +  0) * T_STR + s * 8, T_STR);
            wmma::load_matrix_sync(af[1], St + (mi * 32 + 16) * T_STR + s * 8, T_STR);
            wmma::fragment<wmma::matrix_b, 16, 16, 8, wmma::precision::tf32,
                           wmma::col_major> bf[2];
            wmma::load_matrix_sync(bf[0], St + F_B + (nh * 32 +  0) * T_STR + s * 8, T_STR);
            wmma::load_matrix_sync(bf[1], St + F_B + (nh * 32 + 16) * T_STR + s * 8, T_STR);
            // no __float_to_tf32: HMMA.TF32 truncates fp32 inputs in HW
            wmma::mma_sync(acc[0][0], af[0], bf[0], acc[0][0]);
            wmma::mma_sync(acc[0][1], af[0], bf[1], acc[0][1]);
            wmma::mma_sync(acc[1][0], af[1], bf[0], acc[1][0]);
            wmma::mma_sync(acc[1][1], af[1], bf[1], acc[1][1]);
        }
    }
    __syncthreads();   // all compute done before C scratch overwrites stages

    // ---- store C (128x68) into stage region ----
    float* Cs = sm;
    #pragma unroll
    for (int i = 0; i < 2; ++i)
        #pragma unroll
        for (int j = 0; j < 2; ++j)
            wmma::store_matrix_sync(Cs + (mi * 32 + i * 16) * C_STR + nh * 32 + j * 16,
                                    acc[i][j], C_STR, wmma::mem_row_major);
    __syncthreads();

    // ---- logits: 7 FULL warps; 2 threads per row, 2 batches ----
    if (tid < 224) {
        const int t  = tid >> 1;          // 0..111
        const int kg = tid & 1;
        const int bt = (t >= 56);
        const int l  = t - 56 * bt;       // 0..55
        float z = 0.f;
        if (l < KQ) {
            const int crow = bt * 64 + l;
            #pragma unroll
            for (int j = 0; j < 25; ++j) {
                int k = kg + 2 * j;
                if (k < KQ)
                    z += tanhf(Cs[crow * C_STR + k] + sm[F_WGT + 64 * bt + k])
                         * sm[F_WH + k];
            }
        }
        z += __shfl_xor_sync(0xffffffffu, z, 1);
        if (kg == 0 && l < KQ) sm[F_LOG + 64 * bt + l] = z;
    }
    if (tid < 2) sm[F_LOG + 64 * tid + KQ] = g_sent[2 * b + tid];
    __syncthreads();

    // ---- two softmaxes: warp 0 -> batch 0, warp 1 -> batch 1 ----
    if (tid < 64) {
        const int w  = tid >> 5;
        const int tx = tid & 31;
        const float* sLog = sm + F_LOG + 64 * w;
        float* sProb = sm + F_PROB + 64 * w;
        float v0 = (tx < 50) ? sLog[tx] : -3.402823466e38f;
        float v1 = (tx < 18) ? sLog[tx + 32] : -3.402823466e38f;
        float m = fmaxf(v0, v1);
        #pragma unroll
        for (int off = 16; off; off >>= 1)
            m = fmaxf(m, __shfl_xor_sync(0xffffffffu, m, off));
        float e0 = (tx < 50) ? expf(v0 - m) : 0.f;
        float e1 = (tx < 18) ? expf(v1 - m) : 0.f;
        float ssum = e0 + e1;
        #pragma unroll
        for (int off = 16; off; off >>= 1)
            ssum += __shfl_xor_sync(0xffffffffu, ssum, off);
        float inv = 1.f / ssum;
        if (tx < 50) sProb[tx] = e0 * inv;
        if (tx < 18) sProb[tx + 32] = e1 * inv;
    }
    __syncthreads();

    // ---- phase 2: both batches ----
    #pragma unroll
    for (int bb = 0; bb < 2; ++bb) {
        const float* sProb = sm + F_PROB + 64 * bb;
        const float beta = sProb[KQ];
        float pr[KQ];
        #pragma unroll
        for (int l = 0; l < KQ; ++l) pr[l] = sProb[l];

        const float* Vx = V + (size_t)(2 * b + bb) * KQ * DQ;
        const size_t base = (size_t)(2 * b + bb) * DQ;
        for (int d = tid; d < DQ; d += 256) {
            float cacc = 0.f;
            #pragma unroll
            for (int l = 0; l < KQ; ++l)
                cacc = fmaf(pr[l], __ldg(Vx + (size_t)l * DQ + d), cacc);
            out[base + d] = fmaf(beta, s_t[base + d],
                            fmaf(1.f - beta, cacc, h_t[base + d]));
        }
    }
}

// ---------------------------------------------------------------------------
extern "C" void kernel_launch(void* const* d_in, const int* in_sizes, int n_in,
                              void* d_out, int out_size) {
    (void)in_sizes; (void)n_in; (void)out_size;
    const float* V     = (const float*)d_in[0];
    const float* h_t   = (const float*)d_in[1];
    const float* s_t   = (const float*)d_in[2];
    const float* W_v   = (const float*)d_in[3];
    const float* W_g   = (const float*)d_in[4];
    const float* W_s   = (const float*)d_in[5];
    const float* w_h   = (const float*)d_in[6];
    const float* w_h_s = (const float*)d_in[7];
    float* out = (float*)d_out;

    k_wgt_sent<<<BQ / A_BM, 256>>>(h_t, s_t, W_g, W_s, w_h_s);

    cudaFuncSetAttribute(k_main, cudaFuncAttributeMaxDynamicSharedMemorySize,
                         SMEM_BYTES);
    k_main<<<BQ / BPC, 256, SMEM_BYTES>>>(V, h_t, s_t, W_v, w_h, out);
}